// round 1
// baseline (speedup 1.0000x reference)
#include <cuda_runtime.h>
#include <cuda_bf16.h>
#include <math.h>

#define BSZ 128
#define TLEN 256
#define DMODEL 512
#define NHEADS 8
#define HDIM 64
#define MROWS (BSZ * TLEN)          // 32768

// Scratch: __device__ globals (allocation-free rule).
__device__ float g_qkv[(size_t)MROWS * 3 * DMODEL];  // [32768, 1536]
__device__ float g_y[(size_t)MROWS * DMODEL];        // [32768, 512]

// ---------------------------------------------------------------------------
// SGEMM: C[M,N] = A[M,K] @ W[K,N] + bias[N]
// BM=BN=128, BK=8, 256 threads, 8x8 per thread.
// ---------------------------------------------------------------------------
__global__ __launch_bounds__(256, 2)
void sgemm_bias_kernel(const float* __restrict__ A,
                       const float* __restrict__ W,
                       const float* __restrict__ bias,
                       float* __restrict__ C,
                       int M, int N, int K) {
    constexpr int BM = 128, BN = 128, BK = 8, TM = 8, TN = 8;
    __shared__ float As[BK][BM];
    __shared__ float Bs[BK][BN];

    const int tid = threadIdx.x;
    const int tr = tid / (BN / TN);   // 0..15
    const int tc = tid % (BN / TN);   // 0..15

    const int aRow = tid / 2;                 // 0..127
    const int aCol = (tid % 2) * 4;           // 0 or 4
    const int bRow = tid / 32;                // 0..7
    const int bCol = (tid % 32) * 4;          // 0..124

    const float* Ab = A + (size_t)(blockIdx.y * BM) * K;
    const float* Wb = W + blockIdx.x * BN;

    float acc[TM][TN];
#pragma unroll
    for (int i = 0; i < TM; i++)
#pragma unroll
        for (int j = 0; j < TN; j++) acc[i][j] = 0.0f;

    for (int k0 = 0; k0 < K; k0 += BK) {
        float4 a4 = *(const float4*)(Ab + (size_t)aRow * K + k0 + aCol);
        As[aCol + 0][aRow] = a4.x;
        As[aCol + 1][aRow] = a4.y;
        As[aCol + 2][aRow] = a4.z;
        As[aCol + 3][aRow] = a4.w;
        float4 b4 = *(const float4*)(Wb + (size_t)(k0 + bRow) * N + bCol);
        *(float4*)&Bs[bRow][bCol] = b4;
        __syncthreads();

#pragma unroll
        for (int k = 0; k < BK; k++) {
            float ra[TM], rb[TN];
#pragma unroll
            for (int i = 0; i < TM; i++) ra[i] = As[k][tr * TM + i];
#pragma unroll
            for (int j = 0; j < TN; j++) rb[j] = Bs[k][tc * TN + j];
#pragma unroll
            for (int i = 0; i < TM; i++)
#pragma unroll
                for (int j = 0; j < TN; j++) acc[i][j] += ra[i] * rb[j];
        }
        __syncthreads();
    }

#pragma unroll
    for (int i = 0; i < TM; i++) {
        const int row = blockIdx.y * BM + tr * TM + i;
#pragma unroll
        for (int j = 0; j < TN; j += 4) {
            const int col = blockIdx.x * BN + tc * TN + j;
            float4 o;
            o.x = acc[i][j + 0] + bias[col + 0];
            o.y = acc[i][j + 1] + bias[col + 1];
            o.z = acc[i][j + 2] + bias[col + 2];
            o.w = acc[i][j + 3] + bias[col + 3];
            *(float4*)(C + (size_t)row * N + col) = o;
        }
    }
}

// ---------------------------------------------------------------------------
// Attention: one block per (b,h). K^T (padded stride 257) + V in smem.
// 8 warps, each warp processes query rows t = warp, warp+8, ... (interleaved
// for causal load balance). Per row: dense scores over 256 keys (invalid ->
// -inf), softmax in-warp, then P @ V with P staged in smem.
// ---------------------------------------------------------------------------
#define KT_STRIDE 257
#define ATTN_SMEM_FLOATS (64 * KT_STRIDE + 256 * 64 + 8 * 64 + 8 * 256)

__global__ __launch_bounds__(256, 1)
void attn_kernel(const float* __restrict__ qkv, float* __restrict__ y) {
    extern __shared__ float sm[];
    float* Kt = sm;                         // [64][257]
    float* Vs = Kt + 64 * KT_STRIDE;        // [256][64]
    float* qs = Vs + 256 * 64;              // [8][64]
    float* ps = qs + 8 * 64;                // [8][256]

    const int b = blockIdx.x / NHEADS;
    const int h = blockIdx.x % NHEADS;
    const int tid = threadIdx.x;
    const int warp = tid >> 5;
    const int lane = tid & 31;
    const float scale = 0.125f;  // 1/sqrt(64)

    const float* base = qkv + (size_t)b * TLEN * (3 * DMODEL) + h * HDIM;

    // Load K (transposed, padded) and V. tid-consecutive -> d consecutive:
    // global loads coalesced; Kt store stride 257 -> conflict-free.
    for (int idx = tid; idx < TLEN * HDIM; idx += 256) {
        const int j = idx >> 6;        // key index
        const int d = idx & 63;        // dim
        Kt[d * KT_STRIDE + j] = base[(size_t)j * (3 * DMODEL) + DMODEL + d];
        Vs[j * HDIM + d]      = base[(size_t)j * (3 * DMODEL) + 2 * DMODEL + d];
    }
    __syncthreads();

    float* qw = qs + warp * 64;
    float* pw = ps + warp * 256;

    for (int t = warp; t < TLEN; t += 8) {
        // stage q row
        qw[lane]      = base[(size_t)t * (3 * DMODEL) + lane];
        qw[lane + 32] = base[(size_t)t * (3 * DMODEL) + lane + 32];
        // zero p row
#pragma unroll
        for (int c = 0; c < 8; c++) pw[c * 32 + lane] = 0.0f;
        __syncwarp();

        const int nj = t + 1;
        const int nchunk = (nj + 31) >> 5;
        float s[8];
        float m = -1e30f;
#pragma unroll
        for (int c = 0; c < 8; c++) {
            if (c < nchunk) {
                const int j = c * 32 + lane;
                float accs = 0.0f;
#pragma unroll
                for (int d = 0; d < 64; d++)
                    accs += qw[d] * Kt[d * KT_STRIDE + j];
                accs *= scale;
                if (j >= nj) accs = -1e30f;
                s[c] = accs;
                m = fmaxf(m, accs);
            } else {
                s[c] = -1e30f;
            }
        }
#pragma unroll
        for (int o = 16; o; o >>= 1) m = fmaxf(m, __shfl_xor_sync(0xffffffffu, m, o));

        float lsum = 0.0f;
#pragma unroll
        for (int c = 0; c < 8; c++) {
            if (c < nchunk) {
                const int j = c * 32 + lane;
                float e = __expf(s[c] - m);
                if (j >= nj) e = 0.0f;
                s[c] = e;
                lsum += e;
            }
        }
#pragma unroll
        for (int o = 16; o; o >>= 1) lsum += __shfl_xor_sync(0xffffffffu, lsum, o);
        const float inv = 1.0f / lsum;
#pragma unroll
        for (int c = 0; c < 8; c++) {
            if (c < nchunk) pw[c * 32 + lane] = s[c] * inv;
        }
        __syncwarp();

        // o[d] = sum_j p[j] * V[j][d]; lane owns dims (lane, lane+32)
        float o0 = 0.0f, o1 = 0.0f;
#pragma unroll 4
        for (int j = 0; j < nj; j++) {
            const float p = pw[j];
            o0 += p * Vs[j * HDIM + lane];
            o1 += p * Vs[j * HDIM + lane + 32];
        }
        const size_t yoff = ((size_t)(b * TLEN + t)) * DMODEL + h * HDIM;
        y[yoff + lane]      = o0;
        y[yoff + lane + 32] = o1;
        __syncwarp();
    }
}

// ---------------------------------------------------------------------------
extern "C" void kernel_launch(void* const* d_in, const int* in_sizes, int n_in,
                              void* d_out, int out_size) {
    const float* x     = (const float*)d_in[0];
    const float* W_qkv = (const float*)d_in[1];
    const float* b_qkv = (const float*)d_in[2];
    const float* W_out = (const float*)d_in[3];
    const float* b_out = (const float*)d_in[4];
    float* out = (float*)d_out;

    float* qkv = nullptr;
    float* y   = nullptr;
    cudaGetSymbolAddress((void**)&qkv, g_qkv);
    cudaGetSymbolAddress((void**)&y, g_y);

    const size_t attn_smem = ATTN_SMEM_FLOATS * sizeof(float);
    cudaFuncSetAttribute(attn_kernel,
                         cudaFuncAttributeMaxDynamicSharedMemorySize,
                         (int)attn_smem);

    // 1) QKV projection: [32768,512] @ [512,1536] + b
    dim3 g1(3 * DMODEL / 128, MROWS / 128);
    sgemm_bias_kernel<<<g1, 256>>>(x, W_qkv, b_qkv, qkv, MROWS, 3 * DMODEL, DMODEL);

    // 2) Attention per (b,h)
    attn_kernel<<<BSZ * NHEADS, 256, attn_smem>>>(qkv, y);

    // 3) Output projection: [32768,512] @ [512,512] + b
    dim3 g3(DMODEL / 128, MROWS / 128);
    sgemm_bias_kernel<<<g3, 256>>>(y, W_out, b_out, out, MROWS, DMODEL, DMODEL);
}

// round 3
// speedup vs baseline: 1.6025x; 1.6025x over previous
#include <cuda_runtime.h>
#include <cuda_bf16.h>
#include <math.h>
#include <cstdint>

#define BSZ 128
#define TLEN 256
#define DMODEL 512
#define NHEADS 8
#define HDIM 64
#define MROWS (BSZ * TLEN)          // 32768
#define GK 512                       // K dim of both GEMMs

// ---------------------------------------------------------------------------
// Scratch: __device__ globals (allocation-free rule).
// ---------------------------------------------------------------------------
__device__ float g_qkv[(size_t)MROWS * 3 * DMODEL];   // [32768,1536]
__device__ float g_y[(size_t)MROWS * DMODEL];         // [32768,512]
__device__ __nv_bfloat16 g_ah[(size_t)MROWS * GK];    // A hi (x or y)
__device__ __nv_bfloat16 g_al[(size_t)MROWS * GK];    // A lo
__device__ __nv_bfloat16 g_bh[(size_t)(3 * DMODEL) * GK];  // W_qkv^T hi [1536,512]
__device__ __nv_bfloat16 g_bl[(size_t)(3 * DMODEL) * GK];
__device__ __nv_bfloat16 g_b2h[(size_t)DMODEL * GK];       // W_out^T hi [512,512]
__device__ __nv_bfloat16 g_b2l[(size_t)DMODEL * GK];

// ---------------------------------------------------------------------------
// PTX helpers — ONLY plain-sm_103-legal instructions (sm_80-era):
// mma.sync / ldmatrix / cp.async. NO tcgen05/TMA (need sm_103a target).
// ---------------------------------------------------------------------------
__device__ __forceinline__ uint32_t smem_to_u32(const void* smem_ptr) {
    uint32_t addr;
    asm("{ .reg .u64 tmp; cvta.to.shared.u64 tmp, %1; cvt.u32.u64 %0, tmp; }"
        : "=r"(addr) : "l"(smem_ptr));
    return addr;
}

__device__ __forceinline__ void ldsm_x4(uint32_t* r, uint32_t addr) {
    asm volatile("ldmatrix.sync.aligned.m8n8.x4.shared.b16 {%0,%1,%2,%3}, [%4];"
                 : "=r"(r[0]), "=r"(r[1]), "=r"(r[2]), "=r"(r[3]) : "r"(addr));
}

__device__ __forceinline__ void mma16816(float* c, const uint32_t* a,
                                         const uint32_t* b) {
    asm volatile(
        "mma.sync.aligned.m16n8k16.row.col.f32.bf16.bf16.f32 "
        "{%0,%1,%2,%3}, {%4,%5,%6,%7}, {%8,%9}, {%0,%1,%2,%3};"
        : "+f"(c[0]), "+f"(c[1]), "+f"(c[2]), "+f"(c[3])
        : "r"(a[0]), "r"(a[1]), "r"(a[2]), "r"(a[3]), "r"(b[0]), "r"(b[1]));
}

__device__ __forceinline__ void cp_async16(uint32_t saddr, const void* gaddr) {
    asm volatile("cp.async.cg.shared.global [%0], [%1], 16;"
                 :: "r"(saddr), "l"(gaddr));
}
#define CP_COMMIT() asm volatile("cp.async.commit_group;" ::: "memory")
#define CP_WAIT(n)  asm volatile("cp.async.wait_group %0;" :: "n"(n) : "memory")

// ---------------------------------------------------------------------------
// Precision-split conversion kernels
// ---------------------------------------------------------------------------
__global__ void split_bf16_kernel(const float* __restrict__ in,
                                  __nv_bfloat16* __restrict__ hi,
                                  __nv_bfloat16* __restrict__ lo, int n4) {
    int i = blockIdx.x * blockDim.x + threadIdx.x;
    if (i >= n4) return;
    float4 v = ((const float4*)in)[i];
    float vv[4] = {v.x, v.y, v.z, v.w};
    __nv_bfloat16 hb[4], lb[4];
#pragma unroll
    for (int j = 0; j < 4; j++) {
        hb[j] = __float2bfloat16(vv[j]);
        lb[j] = __float2bfloat16(vv[j] - __bfloat162float(hb[j]));
    }
    __nv_bfloat162* h2 = (__nv_bfloat162*)(hi + (size_t)i * 4);
    __nv_bfloat162* l2 = (__nv_bfloat162*)(lo + (size_t)i * 4);
    h2[0] = __halves2bfloat162(hb[0], hb[1]);
    h2[1] = __halves2bfloat162(hb[2], hb[3]);
    l2[0] = __halves2bfloat162(lb[0], lb[1]);
    l2[1] = __halves2bfloat162(lb[2], lb[3]);
}

// W[K,N] fp32 -> Wt hi/lo [N,K] bf16 (transpose + split)
__global__ void splitT_bf16_kernel(const float* __restrict__ W,
                                   __nv_bfloat16* __restrict__ th,
                                   __nv_bfloat16* __restrict__ tl,
                                   int K, int N) {
    int idx = blockIdx.x * blockDim.x + threadIdx.x;
    if (idx >= K * N) return;
    int k = idx / N, n = idx % N;
    float v = W[idx];
    __nv_bfloat16 h = __float2bfloat16(v);
    th[(size_t)n * K + k] = h;
    tl[(size_t)n * K + k] = __float2bfloat16(v - __bfloat162float(h));
}

// ---------------------------------------------------------------------------
// bf16x3 mma.sync GEMM: C[M,N] = (Ah+Al)[M,K] @ (Bh+Bl)[N,K]^T + bias
// 128x128 block tile, 8 warps (4Mx2N), warp tile 32x64, BK=32, double buffer.
// Row stride 80B (5 x 16B) -> ldmatrix conflict-free (5r+c is perm mod 8).
// ---------------------------------------------------------------------------
#define ROWB 80
#define SM_TILE (128 * ROWB)          // 10240
#define SM_T_AH 0
#define SM_T_AL (SM_TILE)
#define SM_T_BH (2 * SM_TILE)
#define SM_T_BL (3 * SM_TILE)
#define SM_STAGE (4 * SM_TILE)        // 40960
#define GEMM_SMEM (2 * SM_STAGE)      // 81920

__global__ __launch_bounds__(256, 1)
void gemm_mma_kernel(const __nv_bfloat16* __restrict__ Ah,
                     const __nv_bfloat16* __restrict__ Al,
                     const __nv_bfloat16* __restrict__ Bh,
                     const __nv_bfloat16* __restrict__ Bl,
                     const float* __restrict__ bias,
                     float* __restrict__ C, int N) {
    extern __shared__ char smem[];
    const uint32_t sbase = smem_to_u32(smem);
    const int tid = threadIdx.x;
    const int wid = tid >> 5, lane = tid & 31;
    const int warpM = wid & 3, warpN = wid >> 2;
    const int m0 = blockIdx.y * 128, n0 = blockIdx.x * 128;

    const char* gAh = (const char*)(Ah + (size_t)m0 * GK);
    const char* gAl = (const char*)(Al + (size_t)m0 * GK);
    const char* gBh = (const char*)(Bh + (size_t)n0 * GK);
    const char* gBl = (const char*)(Bl + (size_t)n0 * GK);

    float acc[2][8][4];
#pragma unroll
    for (int mt = 0; mt < 2; mt++)
#pragma unroll
        for (int nt = 0; nt < 8; nt++)
#pragma unroll
            for (int r = 0; r < 4; r++) acc[mt][nt][r] = 0.0f;

    const int lr2 = (tid >> 2);          // load row 0..63 (p adds 64)
    const int lc2 = (tid & 3);           // load chunk 0..3

    // ---- prefetch stage 0 ----
    {
        uint32_t sb = sbase;
#pragma unroll
        for (int p = 0; p < 2; p++) {
            int r = lr2 + p * 64;
            uint32_t so = r * ROWB + lc2 * 16;
            size_t go = (size_t)r * (GK * 2) + lc2 * 16;
            cp_async16(sb + SM_T_AH + so, gAh + go);
            cp_async16(sb + SM_T_AL + so, gAl + go);
            cp_async16(sb + SM_T_BH + so, gBh + go);
            cp_async16(sb + SM_T_BL + so, gBl + go);
        }
        CP_COMMIT();
    }

    const int lrow = lane & 15;
    const int lcs = lane >> 4;

    constexpr int NSTAGES = GK / 32;     // 16
    for (int s = 0; s < NSTAGES; s++) {
        if (s + 1 < NSTAGES) {
            uint32_t sb = sbase + ((s + 1) & 1) * SM_STAGE;
            const int kbyte = (s + 1) * 64;
#pragma unroll
            for (int p = 0; p < 2; p++) {
                int r = lr2 + p * 64;
                uint32_t so = r * ROWB + lc2 * 16;
                size_t go = (size_t)r * (GK * 2) + kbyte + lc2 * 16;
                cp_async16(sb + SM_T_AH + so, gAh + go);
                cp_async16(sb + SM_T_AL + so, gAl + go);
                cp_async16(sb + SM_T_BH + so, gBh + go);
                cp_async16(sb + SM_T_BL + so, gBl + go);
            }
            CP_COMMIT();
            CP_WAIT(1);
        } else {
            CP_WAIT(0);
        }
        __syncthreads();

        const uint32_t sb = sbase + (s & 1) * SM_STAGE;
#pragma unroll
        for (int kk = 0; kk < 2; kk++) {
            const uint32_t coff = (kk * 2 + lcs) * 16;
            uint32_t aH[2][4], aL[2][4];
#pragma unroll
            for (int mt = 0; mt < 2; mt++) {
                uint32_t ro = (uint32_t)(warpM * 32 + mt * 16 + lrow) * ROWB + coff;
                ldsm_x4(aH[mt], sb + SM_T_AH + ro);
                ldsm_x4(aL[mt], sb + SM_T_AL + ro);
            }
            uint32_t bH[8][2], bL[8][2];
#pragma unroll
            for (int q = 0; q < 4; q++) {
                uint32_t ro = (uint32_t)(warpN * 64 + q * 16 + lrow) * ROWB + coff;
                uint32_t t[4];
                ldsm_x4(t, sb + SM_T_BH + ro);
                bH[2 * q][0] = t[0]; bH[2 * q][1] = t[2];
                bH[2 * q + 1][0] = t[1]; bH[2 * q + 1][1] = t[3];
                ldsm_x4(t, sb + SM_T_BL + ro);
                bL[2 * q][0] = t[0]; bL[2 * q][1] = t[2];
                bL[2 * q + 1][0] = t[1]; bL[2 * q + 1][1] = t[3];
            }
#pragma unroll
            for (int mt = 0; mt < 2; mt++)
#pragma unroll
                for (int nt = 0; nt < 8; nt++) {
                    mma16816(acc[mt][nt], aH[mt], bH[nt]);
                    mma16816(acc[mt][nt], aH[mt], bL[nt]);
                    mma16816(acc[mt][nt], aL[mt], bH[nt]);
                }
        }
        __syncthreads();
    }

    // ---- epilogue: direct global stores + bias ----
    const int g = lane >> 2, tc4 = lane & 3;
#pragma unroll
    for (int mt = 0; mt < 2; mt++) {
        const int row = m0 + warpM * 32 + mt * 16 + g;
#pragma unroll
        for (int nt = 0; nt < 8; nt++) {
            const int col = n0 + warpN * 64 + nt * 8 + tc4 * 2;
            const float bv0 = bias[col], bv1 = bias[col + 1];
            float2 v0, v1;
            v0.x = acc[mt][nt][0] + bv0; v0.y = acc[mt][nt][1] + bv1;
            v1.x = acc[mt][nt][2] + bv0; v1.y = acc[mt][nt][3] + bv1;
            *(float2*)(C + (size_t)row * N + col) = v0;
            *(float2*)(C + (size_t)(row + 8) * N + col) = v1;
        }
    }
}

// ---------------------------------------------------------------------------
// Attention: one block per (b,h). K^T (padded stride 257) + V in smem.
// ---------------------------------------------------------------------------
#define KT_STRIDE 257
#define ATTN_SMEM_FLOATS (64 * KT_STRIDE + 256 * 64 + 8 * 64 + 8 * 256)

__global__ __launch_bounds__(256, 1)
void attn_kernel(const float* __restrict__ qkv, float* __restrict__ y) {
    extern __shared__ float sm[];
    float* Kt = sm;                         // [64][257]
    float* Vs = Kt + 64 * KT_STRIDE;        // [256][64]
    float* qs = Vs + 256 * 64;              // [8][64]
    float* ps = qs + 8 * 64;                // [8][256]

    const int b = blockIdx.x / NHEADS;
    const int h = blockIdx.x % NHEADS;
    const int tid = threadIdx.x;
    const int warp = tid >> 5;
    const int lane = tid & 31;
    const float scale = 0.125f;

    const float* base = qkv + (size_t)b * TLEN * (3 * DMODEL) + h * HDIM;

    for (int idx = tid; idx < TLEN * HDIM; idx += 256) {
        const int j = idx >> 6;
        const int d = idx & 63;
        Kt[d * KT_STRIDE + j] = base[(size_t)j * (3 * DMODEL) + DMODEL + d];
        Vs[j * HDIM + d]      = base[(size_t)j * (3 * DMODEL) + 2 * DMODEL + d];
    }
    __syncthreads();

    float* qw = qs + warp * 64;
    float* pw = ps + warp * 256;

    for (int t = warp; t < TLEN; t += 8) {
        qw[lane]      = base[(size_t)t * (3 * DMODEL) + lane];
        qw[lane + 32] = base[(size_t)t * (3 * DMODEL) + lane + 32];
#pragma unroll
        for (int c = 0; c < 8; c++) pw[c * 32 + lane] = 0.0f;
        __syncwarp();

        const int nj = t + 1;
        const int nchunk = (nj + 31) >> 5;
        float s[8];
        float m = -1e30f;
#pragma unroll
        for (int c = 0; c < 8; c++) {
            if (c < nchunk) {
                const int j = c * 32 + lane;
                float accs = 0.0f;
#pragma unroll
                for (int d = 0; d < 64; d++)
                    accs += qw[d] * Kt[d * KT_STRIDE + j];
                accs *= scale;
                if (j >= nj) accs = -1e30f;
                s[c] = accs;
                m = fmaxf(m, accs);
            } else {
                s[c] = -1e30f;
            }
        }
#pragma unroll
        for (int o = 16; o; o >>= 1) m = fmaxf(m, __shfl_xor_sync(0xffffffffu, m, o));

        float lsum = 0.0f;
#pragma unroll
        for (int c = 0; c < 8; c++) {
            if (c < nchunk) {
                const int j = c * 32 + lane;
                float e = __expf(s[c] - m);
                if (j >= nj) e = 0.0f;
                s[c] = e;
                lsum += e;
            }
        }
#pragma unroll
        for (int o = 16; o; o >>= 1) lsum += __shfl_xor_sync(0xffffffffu, lsum, o);
        const float inv = 1.0f / lsum;
#pragma unroll
        for (int c = 0; c < 8; c++) {
            if (c < nchunk) pw[c * 32 + lane] = s[c] * inv;
        }
        __syncwarp();

        float o0 = 0.0f, o1 = 0.0f;
#pragma unroll 4
        for (int j = 0; j < nj; j++) {
            const float p = pw[j];
            o0 += p * Vs[j * HDIM + lane];
            o1 += p * Vs[j * HDIM + lane + 32];
        }
        const size_t yoff = ((size_t)(b * TLEN + t)) * DMODEL + h * HDIM;
        y[yoff + lane]      = o0;
        y[yoff + lane + 32] = o1;
        __syncwarp();
    }
}

// ---------------------------------------------------------------------------
extern "C" void kernel_launch(void* const* d_in, const int* in_sizes, int n_in,
                              void* d_out, int out_size) {
    const float* x     = (const float*)d_in[0];
    const float* W_qkv = (const float*)d_in[1];
    const float* b_qkv = (const float*)d_in[2];
    const float* W_out = (const float*)d_in[3];
    const float* b_out = (const float*)d_in[4];
    float* out = (float*)d_out;

    float *qkv, *y;
    __nv_bfloat16 *ah, *al, *bh, *bl, *b2h, *b2l;
    cudaGetSymbolAddress((void**)&qkv, g_qkv);
    cudaGetSymbolAddress((void**)&y, g_y);
    cudaGetSymbolAddress((void**)&ah, g_ah);
    cudaGetSymbolAddress((void**)&al, g_al);
    cudaGetSymbolAddress((void**)&bh, g_bh);
    cudaGetSymbolAddress((void**)&bl, g_bl);
    cudaGetSymbolAddress((void**)&b2h, g_b2h);
    cudaGetSymbolAddress((void**)&b2l, g_b2l);

    const size_t attn_smem = ATTN_SMEM_FLOATS * sizeof(float);
    cudaFuncSetAttribute(attn_kernel,
                         cudaFuncAttributeMaxDynamicSharedMemorySize,
                         (int)attn_smem);
    cudaFuncSetAttribute(gemm_mma_kernel,
                         cudaFuncAttributeMaxDynamicSharedMemorySize, GEMM_SMEM);

    // 1) split x -> bf16 hi/lo
    {
        const int n4 = MROWS * GK / 4;
        split_bf16_kernel<<<(n4 + 255) / 256, 256>>>(x, ah, al, n4);
    }
    // 2) split+transpose weights
    splitT_bf16_kernel<<<(GK * 3 * DMODEL + 255) / 256, 256>>>(W_qkv, bh, bl,
                                                               GK, 3 * DMODEL);
    splitT_bf16_kernel<<<(GK * DMODEL + 255) / 256, 256>>>(W_out, b2h, b2l,
                                                           GK, DMODEL);

    // 3) QKV projection on tensor cores (mma.sync bf16x3)
    {
        dim3 g(3 * DMODEL / 128, MROWS / 128);
        gemm_mma_kernel<<<g, 256, GEMM_SMEM>>>(ah, al, bh, bl, b_qkv, qkv,
                                               3 * DMODEL);
    }

    // 4) attention
    attn_kernel<<<BSZ * NHEADS, 256, attn_smem>>>(qkv, y);

    // 5) split y -> bf16 hi/lo (reuse buffers)
    {
        const int n4 = MROWS * GK / 4;
        split_bf16_kernel<<<(n4 + 255) / 256, 256>>>(y, ah, al, n4);
    }

    // 6) output projection on tensor cores
    {
        dim3 g(DMODEL / 128, MROWS / 128);
        gemm_mma_kernel<<<g, 256, GEMM_SMEM>>>(ah, al, b2h, b2l, b_out, out,
                                               DMODEL);
    }
}

// round 4
// speedup vs baseline: 2.6267x; 1.6391x over previous
#include <cuda_runtime.h>
#include <cuda_bf16.h>
#include <math.h>
#include <cstdint>

#define BSZ 128
#define TLEN 256
#define DMODEL 512
#define NHEADS 8
#define HDIM 64
#define MROWS (BSZ * TLEN)          // 32768
#define GK 512                       // K dim of both GEMMs

// ---------------------------------------------------------------------------
// Scratch: __device__ globals (allocation-free rule).
// ---------------------------------------------------------------------------
__device__ float g_qkv[(size_t)MROWS * 3 * DMODEL];   // [32768,1536]
__device__ __nv_bfloat16 g_ah[(size_t)MROWS * GK];    // A hi (x, then attn out)
__device__ __nv_bfloat16 g_al[(size_t)MROWS * GK];    // A lo
__device__ __nv_bfloat16 g_bh[(size_t)(3 * DMODEL) * GK];  // W_qkv^T hi
__device__ __nv_bfloat16 g_bl[(size_t)(3 * DMODEL) * GK];
__device__ __nv_bfloat16 g_b2h[(size_t)DMODEL * GK];       // W_out^T hi
__device__ __nv_bfloat16 g_b2l[(size_t)DMODEL * GK];

// ---------------------------------------------------------------------------
// PTX helpers — plain-sm_103-legal only (mma.sync / ldmatrix / cp.async).
// ---------------------------------------------------------------------------
__device__ __forceinline__ uint32_t smem_to_u32(const void* smem_ptr) {
    uint32_t addr;
    asm("{ .reg .u64 tmp; cvta.to.shared.u64 tmp, %1; cvt.u32.u64 %0, tmp; }"
        : "=r"(addr) : "l"(smem_ptr));
    return addr;
}

__device__ __forceinline__ void ldsm_x4(uint32_t* r, uint32_t addr) {
    asm volatile("ldmatrix.sync.aligned.m8n8.x4.shared.b16 {%0,%1,%2,%3}, [%4];"
                 : "=r"(r[0]), "=r"(r[1]), "=r"(r[2]), "=r"(r[3]) : "r"(addr));
}

__device__ __forceinline__ void mma16816(float* c, const uint32_t* a,
                                         const uint32_t* b) {
    asm volatile(
        "mma.sync.aligned.m16n8k16.row.col.f32.bf16.bf16.f32 "
        "{%0,%1,%2,%3}, {%4,%5,%6,%7}, {%8,%9}, {%0,%1,%2,%3};"
        : "+f"(c[0]), "+f"(c[1]), "+f"(c[2]), "+f"(c[3])
        : "r"(a[0]), "r"(a[1]), "r"(a[2]), "r"(a[3]), "r"(b[0]), "r"(b[1]));
}

__device__ __forceinline__ void cp_async16(uint32_t saddr, const void* gaddr) {
    asm volatile("cp.async.cg.shared.global [%0], [%1], 16;"
                 :: "r"(saddr), "l"(gaddr));
}
#define CP_COMMIT() asm volatile("cp.async.commit_group;" ::: "memory")
#define CP_WAIT(n)  asm volatile("cp.async.wait_group %0;" :: "n"(n) : "memory")

__device__ __forceinline__ uint32_t pack_bf16(float a, float b) {
    __nv_bfloat162 t = __floats2bfloat162_rn(a, b);
    return *(uint32_t*)&t;
}

// ---------------------------------------------------------------------------
// Precision-split conversion kernels
// ---------------------------------------------------------------------------
__global__ void split_bf16_kernel(const float* __restrict__ in,
                                  __nv_bfloat16* __restrict__ hi,
                                  __nv_bfloat16* __restrict__ lo, int n4) {
    int i = blockIdx.x * blockDim.x + threadIdx.x;
    if (i >= n4) return;
    float4 v = ((const float4*)in)[i];
    float vv[4] = {v.x, v.y, v.z, v.w};
    __nv_bfloat16 hb[4], lb[4];
#pragma unroll
    for (int j = 0; j < 4; j++) {
        hb[j] = __float2bfloat16(vv[j]);
        lb[j] = __float2bfloat16(vv[j] - __bfloat162float(hb[j]));
    }
    __nv_bfloat162* h2 = (__nv_bfloat162*)(hi + (size_t)i * 4);
    __nv_bfloat162* l2 = (__nv_bfloat162*)(lo + (size_t)i * 4);
    h2[0] = __halves2bfloat162(hb[0], hb[1]);
    h2[1] = __halves2bfloat162(hb[2], hb[3]);
    l2[0] = __halves2bfloat162(lb[0], lb[1]);
    l2[1] = __halves2bfloat162(lb[2], lb[3]);
}

__global__ void splitT_bf16_kernel(const float* __restrict__ W,
                                   __nv_bfloat16* __restrict__ th,
                                   __nv_bfloat16* __restrict__ tl,
                                   int K, int N) {
    int idx = blockIdx.x * blockDim.x + threadIdx.x;
    if (idx >= K * N) return;
    int k = idx / N, n = idx % N;
    float v = W[idx];
    __nv_bfloat16 h = __float2bfloat16(v);
    th[(size_t)n * K + k] = h;
    tl[(size_t)n * K + k] = __float2bfloat16(v - __bfloat162float(h));
}

// ---------------------------------------------------------------------------
// bf16x3 mma.sync GEMM (unchanged from R3)
// ---------------------------------------------------------------------------
#define ROWB 80
#define SM_TILE (128 * ROWB)
#define SM_T_AH 0
#define SM_T_AL (SM_TILE)
#define SM_T_BH (2 * SM_TILE)
#define SM_T_BL (3 * SM_TILE)
#define SM_STAGE (4 * SM_TILE)
#define GEMM_SMEM (2 * SM_STAGE)

__global__ __launch_bounds__(256, 1)
void gemm_mma_kernel(const __nv_bfloat16* __restrict__ Ah,
                     const __nv_bfloat16* __restrict__ Al,
                     const __nv_bfloat16* __restrict__ Bh,
                     const __nv_bfloat16* __restrict__ Bl,
                     const float* __restrict__ bias,
                     float* __restrict__ C, int N) {
    extern __shared__ char smem[];
    const uint32_t sbase = smem_to_u32(smem);
    const int tid = threadIdx.x;
    const int wid = tid >> 5, lane = tid & 31;
    const int warpM = wid & 3, warpN = wid >> 2;
    const int m0 = blockIdx.y * 128, n0 = blockIdx.x * 128;

    const char* gAh = (const char*)(Ah + (size_t)m0 * GK);
    const char* gAl = (const char*)(Al + (size_t)m0 * GK);
    const char* gBh = (const char*)(Bh + (size_t)n0 * GK);
    const char* gBl = (const char*)(Bl + (size_t)n0 * GK);

    float acc[2][8][4];
#pragma unroll
    for (int mt = 0; mt < 2; mt++)
#pragma unroll
        for (int nt = 0; nt < 8; nt++)
#pragma unroll
            for (int r = 0; r < 4; r++) acc[mt][nt][r] = 0.0f;

    const int lr2 = (tid >> 2);
    const int lc2 = (tid & 3);

    {
        uint32_t sb = sbase;
#pragma unroll
        for (int p = 0; p < 2; p++) {
            int r = lr2 + p * 64;
            uint32_t so = r * ROWB + lc2 * 16;
            size_t go = (size_t)r * (GK * 2) + lc2 * 16;
            cp_async16(sb + SM_T_AH + so, gAh + go);
            cp_async16(sb + SM_T_AL + so, gAl + go);
            cp_async16(sb + SM_T_BH + so, gBh + go);
            cp_async16(sb + SM_T_BL + so, gBl + go);
        }
        CP_COMMIT();
    }

    const int lrow = lane & 15;
    const int lcs = lane >> 4;

    constexpr int NSTAGES = GK / 32;
    for (int s = 0; s < NSTAGES; s++) {
        if (s + 1 < NSTAGES) {
            uint32_t sb = sbase + ((s + 1) & 1) * SM_STAGE;
            const int kbyte = (s + 1) * 64;
#pragma unroll
            for (int p = 0; p < 2; p++) {
                int r = lr2 + p * 64;
                uint32_t so = r * ROWB + lc2 * 16;
                size_t go = (size_t)r * (GK * 2) + kbyte + lc2 * 16;
                cp_async16(sb + SM_T_AH + so, gAh + go);
                cp_async16(sb + SM_T_AL + so, gAl + go);
                cp_async16(sb + SM_T_BH + so, gBh + go);
                cp_async16(sb + SM_T_BL + so, gBl + go);
            }
            CP_COMMIT();
            CP_WAIT(1);
        } else {
            CP_WAIT(0);
        }
        __syncthreads();

        const uint32_t sb = sbase + (s & 1) * SM_STAGE;
#pragma unroll
        for (int kk = 0; kk < 2; kk++) {
            const uint32_t coff = (kk * 2 + lcs) * 16;
            uint32_t aH[2][4], aL[2][4];
#pragma unroll
            for (int mt = 0; mt < 2; mt++) {
                uint32_t ro = (uint32_t)(warpM * 32 + mt * 16 + lrow) * ROWB + coff;
                ldsm_x4(aH[mt], sb + SM_T_AH + ro);
                ldsm_x4(aL[mt], sb + SM_T_AL + ro);
            }
            uint32_t bH[8][2], bL[8][2];
#pragma unroll
            for (int q = 0; q < 4; q++) {
                uint32_t ro = (uint32_t)(warpN * 64 + q * 16 + lrow) * ROWB + coff;
                uint32_t t[4];
                ldsm_x4(t, sb + SM_T_BH + ro);
                bH[2 * q][0] = t[0]; bH[2 * q][1] = t[2];
                bH[2 * q + 1][0] = t[1]; bH[2 * q + 1][1] = t[3];
                ldsm_x4(t, sb + SM_T_BL + ro);
                bL[2 * q][0] = t[0]; bL[2 * q][1] = t[2];
                bL[2 * q + 1][0] = t[1]; bL[2 * q + 1][1] = t[3];
            }
#pragma unroll
            for (int mt = 0; mt < 2; mt++)
#pragma unroll
                for (int nt = 0; nt < 8; nt++) {
                    mma16816(acc[mt][nt], aH[mt], bH[nt]);
                    mma16816(acc[mt][nt], aH[mt], bL[nt]);
                    mma16816(acc[mt][nt], aL[mt], bH[nt]);
                }
        }
        __syncthreads();
    }

    const int g = lane >> 2, tc4 = lane & 3;
#pragma unroll
    for (int mt = 0; mt < 2; mt++) {
        const int row = m0 + warpM * 32 + mt * 16 + g;
#pragma unroll
        for (int nt = 0; nt < 8; nt++) {
            const int col = n0 + warpN * 64 + nt * 8 + tc4 * 2;
            const float bv0 = bias[col], bv1 = bias[col + 1];
            float2 v0, v1;
            v0.x = acc[mt][nt][0] + bv0; v0.y = acc[mt][nt][1] + bv1;
            v1.x = acc[mt][nt][2] + bv0; v1.y = acc[mt][nt][3] + bv1;
            *(float2*)(C + (size_t)row * N + col) = v0;
            *(float2*)(C + (size_t)(row + 8) * N + col) = v1;
        }
    }
}

// ---------------------------------------------------------------------------
// Flash attention with mma.sync bf16x3. One block per (b,h), 8 warps.
// Q,K: [256][144B] bf16 hi/lo. Vt: [64][528B] bf16 hi/lo (dim-major).
// Warp w handles m16 tiles {w, 15-w} (balanced causal work: 5 chunk-units).
// Output written directly as bf16 hi/lo into out-GEMM A buffers.
// ---------------------------------------------------------------------------
#define AT_QH 0
#define AT_QL 36864
#define AT_KH 73728
#define AT_KL 110592
#define AT_VTH 147456
#define AT_VTL 181248
#define ATTN_SMEM 215040
#define AT_VSTAGE 0          // fp32 V staging [256][272B], overlaps Q region

__global__ __launch_bounds__(256, 1)
void attn_mma_kernel(const float* __restrict__ qkv,
                     __nv_bfloat16* __restrict__ yh,
                     __nv_bfloat16* __restrict__ yl) {
    extern __shared__ char smem[];
    const uint32_t sbase = smem_to_u32(smem);
    const int b = blockIdx.x >> 3;
    const int h = blockIdx.x & 7;
    const int tid = threadIdx.x;
    const int wid = tid >> 5, lane = tid & 31;
    const int g = lane >> 2, tq = lane & 3;
    const int lrow = lane & 15, lcs = lane >> 4;
    const float SCALE = 0.125f;

    const float* base = qkv + (size_t)b * TLEN * (3 * DMODEL) + h * HDIM;

    // 1) stage V fp32 coalesced into [256][272B]
    for (int i = tid; i < 256 * 16; i += 256) {
        const int t = i >> 4, c = i & 15;
        float4 v = *(const float4*)(base + (size_t)t * (3 * DMODEL) + 2 * DMODEL + c * 4);
        *(float4*)(smem + AT_VSTAGE + t * 272 + c * 16) = v;
    }
    __syncthreads();

    // 2) transpose + split into Vth/Vtl [64][528B]
    {
        const int d = tid & 63;
        const int jb = (tid >> 6) * 64;
#pragma unroll 4
        for (int jp = 0; jp < 32; jp++) {
            const int j = jb + 2 * jp;
            float v0 = *(const float*)(smem + AT_VSTAGE + j * 272 + d * 4);
            float v1 = *(const float*)(smem + AT_VSTAGE + (j + 1) * 272 + d * 4);
            __nv_bfloat16 h0 = __float2bfloat16(v0);
            __nv_bfloat16 h1 = __float2bfloat16(v1);
            __nv_bfloat16 l0 = __float2bfloat16(v0 - __bfloat162float(h0));
            __nv_bfloat16 l1 = __float2bfloat16(v1 - __bfloat162float(h1));
            *(__nv_bfloat162*)(smem + AT_VTH + d * 528 + j * 2) = __halves2bfloat162(h0, h1);
            *(__nv_bfloat162*)(smem + AT_VTL + d * 528 + j * 2) = __halves2bfloat162(l0, l1);
        }
    }
    __syncthreads();   // staging region about to be overwritten by Q

    // 3) load Q,K with split into [256][144B]
    for (int i = tid; i < 256 * 16; i += 256) {
        const int t = i >> 4, c = i & 15;
        const size_t roff = (size_t)t * (3 * DMODEL);
        float4 q = *(const float4*)(base + roff + c * 4);
        float4 k = *(const float4*)(base + roff + DMODEL + c * 4);
        float qv[4] = {q.x, q.y, q.z, q.w};
        float kv[4] = {k.x, k.y, k.z, k.w};
        __nv_bfloat16 qh[4], ql[4], kh[4], kl[4];
#pragma unroll
        for (int j = 0; j < 4; j++) {
            qh[j] = __float2bfloat16(qv[j]);
            ql[j] = __float2bfloat16(qv[j] - __bfloat162float(qh[j]));
            kh[j] = __float2bfloat16(kv[j]);
            kl[j] = __float2bfloat16(kv[j] - __bfloat162float(kh[j]));
        }
        const int so = t * 144 + c * 8;
        *(__nv_bfloat162*)(smem + AT_QH + so)     = __halves2bfloat162(qh[0], qh[1]);
        *(__nv_bfloat162*)(smem + AT_QH + so + 4) = __halves2bfloat162(qh[2], qh[3]);
        *(__nv_bfloat162*)(smem + AT_QL + so)     = __halves2bfloat162(ql[0], ql[1]);
        *(__nv_bfloat162*)(smem + AT_QL + so + 4) = __halves2bfloat162(ql[2], ql[3]);
        *(__nv_bfloat162*)(smem + AT_KH + so)     = __halves2bfloat162(kh[0], kh[1]);
        *(__nv_bfloat162*)(smem + AT_KH + so + 4) = __halves2bfloat162(kh[2], kh[3]);
        *(__nv_bfloat162*)(smem + AT_KL + so)     = __halves2bfloat162(kl[0], kl[1]);
        *(__nv_bfloat162*)(smem + AT_KL + so + 4) = __halves2bfloat162(kl[2], kl[3]);
    }
    __syncthreads();

    // 4) compute: two m16 tiles per warp
#pragma unroll
    for (int half = 0; half < 2; half++) {
        const int tile = (half == 0) ? wid : 15 - wid;
        const int nch = tile / 4 + 1;

        float o[8][4];
#pragma unroll
        for (int nt = 0; nt < 8; nt++)
#pragma unroll
            for (int r = 0; r < 4; r++) o[nt][r] = 0.0f;
        float m0 = -1e30f, m1 = -1e30f, l0 = 0.0f, l1 = 0.0f;

        for (int c = 0; c < nch; c++) {
            float S[8][4];
#pragma unroll
            for (int nt = 0; nt < 8; nt++)
#pragma unroll
                for (int r = 0; r < 4; r++) S[nt][r] = 0.0f;

            // ---- S = Q @ K^T (bf16x3) ----
#pragma unroll
            for (int kt = 0; kt < 4; kt++) {
                uint32_t aH[4], aL[4];
                const uint32_t qro = (uint32_t)(tile * 16 + lrow) * 144 + kt * 32 + lcs * 16;
                ldsm_x4(aH, sbase + AT_QH + qro);
                ldsm_x4(aL, sbase + AT_QL + qro);
#pragma unroll
                for (int q = 0; q < 4; q++) {
                    const uint32_t kro =
                        (uint32_t)(c * 64 + q * 16 + lrow) * 144 + kt * 32 + lcs * 16;
                    uint32_t tH[4], tL[4];
                    ldsm_x4(tH, sbase + AT_KH + kro);
                    ldsm_x4(tL, sbase + AT_KL + kro);
                    uint32_t b0H[2] = {tH[0], tH[2]}, b1H[2] = {tH[1], tH[3]};
                    uint32_t b0L[2] = {tL[0], tL[2]}, b1L[2] = {tL[1], tL[3]};
                    mma16816(S[2 * q],     aH, b0H);
                    mma16816(S[2 * q],     aH, b0L);
                    mma16816(S[2 * q],     aL, b0H);
                    mma16816(S[2 * q + 1], aH, b1H);
                    mma16816(S[2 * q + 1], aH, b1L);
                    mma16816(S[2 * q + 1], aL, b1H);
                }
            }

            // ---- scale + causal mask ----
            const int r0 = tile * 16 + g, r1 = r0 + 8;
            if (c == nch - 1) {
#pragma unroll
                for (int nt = 0; nt < 8; nt++) {
                    const int col = c * 64 + nt * 8 + 2 * tq;
                    S[nt][0] = (col     <= r0) ? S[nt][0] * SCALE : -1e30f;
                    S[nt][1] = (col + 1 <= r0) ? S[nt][1] * SCALE : -1e30f;
                    S[nt][2] = (col     <= r1) ? S[nt][2] * SCALE : -1e30f;
                    S[nt][3] = (col + 1 <= r1) ? S[nt][3] * SCALE : -1e30f;
                }
            } else {
#pragma unroll
                for (int nt = 0; nt < 8; nt++)
#pragma unroll
                    for (int r = 0; r < 4; r++) S[nt][r] *= SCALE;
            }

            // ---- online softmax ----
            float cm0 = -1e30f, cm1 = -1e30f;
#pragma unroll
            for (int nt = 0; nt < 8; nt++) {
                cm0 = fmaxf(cm0, fmaxf(S[nt][0], S[nt][1]));
                cm1 = fmaxf(cm1, fmaxf(S[nt][2], S[nt][3]));
            }
            cm0 = fmaxf(cm0, __shfl_xor_sync(0xffffffffu, cm0, 1));
            cm0 = fmaxf(cm0, __shfl_xor_sync(0xffffffffu, cm0, 2));
            cm1 = fmaxf(cm1, __shfl_xor_sync(0xffffffffu, cm1, 1));
            cm1 = fmaxf(cm1, __shfl_xor_sync(0xffffffffu, cm1, 2));
            const float mn0 = fmaxf(m0, cm0), mn1 = fmaxf(m1, cm1);
            const float a0 = __expf(m0 - mn0), a1 = __expf(m1 - mn1);
            m0 = mn0; m1 = mn1;

            float rs0 = 0.0f, rs1 = 0.0f;
#pragma unroll
            for (int nt = 0; nt < 8; nt++) {
                S[nt][0] = __expf(S[nt][0] - mn0);
                S[nt][1] = __expf(S[nt][1] - mn0);
                S[nt][2] = __expf(S[nt][2] - mn1);
                S[nt][3] = __expf(S[nt][3] - mn1);
                rs0 += S[nt][0] + S[nt][1];
                rs1 += S[nt][2] + S[nt][3];
            }
            rs0 += __shfl_xor_sync(0xffffffffu, rs0, 1);
            rs0 += __shfl_xor_sync(0xffffffffu, rs0, 2);
            rs1 += __shfl_xor_sync(0xffffffffu, rs1, 1);
            rs1 += __shfl_xor_sync(0xffffffffu, rs1, 2);
            l0 = l0 * a0 + rs0;
            l1 = l1 * a1 + rs1;

#pragma unroll
            for (int nt = 0; nt < 8; nt++) {
                o[nt][0] *= a0; o[nt][1] *= a0;
                o[nt][2] *= a1; o[nt][3] *= a1;
            }

            // ---- P frags (hi/lo split) ----
            uint32_t pH[4][4], pL[4][4];
#pragma unroll
            for (int kt = 0; kt < 4; kt++) {
#pragma unroll
                for (int part = 0; part < 4; part++) {
                    const int nt = 2 * kt + (part >> 1);
                    const int rb = (part & 1) * 2;
                    const float p0 = S[nt][rb], p1 = S[nt][rb + 1];
                    __nv_bfloat16 h0 = __float2bfloat16(p0);
                    __nv_bfloat16 h1 = __float2bfloat16(p1);
                    float q0 = p0 - __bfloat162float(h0);
                    float q1 = p1 - __bfloat162float(h1);
                    __nv_bfloat162 hh = __halves2bfloat162(h0, h1);
                    pH[kt][part] = *(uint32_t*)&hh;
                    pL[kt][part] = pack_bf16(q0, q1);
                }
            }

            // ---- O += P @ V (bf16x3) ----
#pragma unroll
            for (int kt = 0; kt < 4; kt++) {
#pragma unroll
                for (int q = 0; q < 4; q++) {
                    const uint32_t vro =
                        (uint32_t)(q * 16 + lrow) * 528 + c * 128 + kt * 32 + lcs * 16;
                    uint32_t tH[4], tL[4];
                    ldsm_x4(tH, sbase + AT_VTH + vro);
                    ldsm_x4(tL, sbase + AT_VTL + vro);
                    uint32_t b0H[2] = {tH[0], tH[2]}, b1H[2] = {tH[1], tH[3]};
                    uint32_t b0L[2] = {tL[0], tL[2]}, b1L[2] = {tL[1], tL[3]};
                    mma16816(o[2 * q],     pH[kt], b0H);
                    mma16816(o[2 * q],     pH[kt], b0L);
                    mma16816(o[2 * q],     pL[kt], b0H);
                    mma16816(o[2 * q + 1], pH[kt], b1H);
                    mma16816(o[2 * q + 1], pH[kt], b1L);
                    mma16816(o[2 * q + 1], pL[kt], b1H);
                }
            }
        }

        // ---- normalize + write bf16 hi/lo ----
        const float inv0 = 1.0f / l0, inv1 = 1.0f / l1;
        const int row0 = b * TLEN + tile * 16 + g;
#pragma unroll
        for (int nt = 0; nt < 8; nt++) {
            const int col = h * HDIM + nt * 8 + 2 * tq;
            const size_t i0 = (size_t)row0 * DMODEL + col;
            const size_t i1 = i0 + (size_t)8 * DMODEL;
            float v0 = o[nt][0] * inv0, v1 = o[nt][1] * inv0;
            float v2 = o[nt][2] * inv1, v3 = o[nt][3] * inv1;
            __nv_bfloat16 h0 = __float2bfloat16(v0), h1 = __float2bfloat16(v1);
            __nv_bfloat16 h2 = __float2bfloat16(v2), h3 = __float2bfloat16(v3);
            *(__nv_bfloat162*)(yh + i0) = __halves2bfloat162(h0, h1);
            *(__nv_bfloat162*)(yh + i1) = __halves2bfloat162(h2, h3);
            *(__nv_bfloat162*)(yl + i0) = __halves2bfloat162(
                __float2bfloat16(v0 - __bfloat162float(h0)),
                __float2bfloat16(v1 - __bfloat162float(h1)));
            *(__nv_bfloat162*)(yl + i1) = __halves2bfloat162(
                __float2bfloat16(v2 - __bfloat162float(h2)),
                __float2bfloat16(v3 - __bfloat162float(h3)));
        }
    }
}

// ---------------------------------------------------------------------------
extern "C" void kernel_launch(void* const* d_in, const int* in_sizes, int n_in,
                              void* d_out, int out_size) {
    const float* x     = (const float*)d_in[0];
    const float* W_qkv = (const float*)d_in[1];
    const float* b_qkv = (const float*)d_in[2];
    const float* W_out = (const float*)d_in[3];
    const float* b_out = (const float*)d_in[4];
    float* out = (float*)d_out;

    float* qkv;
    __nv_bfloat16 *ah, *al, *bh, *bl, *b2h, *b2l;
    cudaGetSymbolAddress((void**)&qkv, g_qkv);
    cudaGetSymbolAddress((void**)&ah, g_ah);
    cudaGetSymbolAddress((void**)&al, g_al);
    cudaGetSymbolAddress((void**)&bh, g_bh);
    cudaGetSymbolAddress((void**)&bl, g_bl);
    cudaGetSymbolAddress((void**)&b2h, g_b2h);
    cudaGetSymbolAddress((void**)&b2l, g_b2l);

    cudaFuncSetAttribute(gemm_mma_kernel,
                         cudaFuncAttributeMaxDynamicSharedMemorySize, GEMM_SMEM);
    cudaFuncSetAttribute(attn_mma_kernel,
                         cudaFuncAttributeMaxDynamicSharedMemorySize, ATTN_SMEM);

    // 1) split x -> bf16 hi/lo
    {
        const int n4 = MROWS * GK / 4;
        split_bf16_kernel<<<(n4 + 255) / 256, 256>>>(x, ah, al, n4);
    }
    // 2) split+transpose weights
    splitT_bf16_kernel<<<(GK * 3 * DMODEL + 255) / 256, 256>>>(W_qkv, bh, bl,
                                                               GK, 3 * DMODEL);
    splitT_bf16_kernel<<<(GK * DMODEL + 255) / 256, 256>>>(W_out, b2h, b2l,
                                                           GK, DMODEL);

    // 3) QKV projection (tensor cores)
    {
        dim3 g(3 * DMODEL / 128, MROWS / 128);
        gemm_mma_kernel<<<g, 256, GEMM_SMEM>>>(ah, al, bh, bl, b_qkv, qkv,
                                               3 * DMODEL);
    }

    // 4) flash attention (tensor cores), writes bf16 hi/lo into ah/al
    attn_mma_kernel<<<BSZ * NHEADS, 256, ATTN_SMEM>>>(qkv, ah, al);

    // 5) output projection (tensor cores)
    {
        dim3 g(DMODEL / 128, MROWS / 128);
        gemm_mma_kernel<<<g, 256, GEMM_SMEM>>>(ah, al, b2h, b2l, b_out, out,
                                               DMODEL);
    }
}